// round 3
// baseline (speedup 1.0000x reference)
#include <cuda_runtime.h>

#define NCHUNKS 32
#define WARPS   8
#define ROWS    64
#define THREADS 256
#define XPAD    257               // smem row stride in floats (conflict-free)
#define UNROLL  8
#define MAX_ATOMS   16384
#define MAX_CLAUSES 4096

// Packed per-atom metadata: {A', B', fid|lastFlag(bit31), g_gl[cid] if last else 0}
// arg = A'*x[fid] + B' ;  e = exp2(arg) = exp(-z) ;  sigmoid(z) = 1/(1+e)
// clause value = 1 / prod(1+e) ; flushed when lastFlag set.
__device__ float4 g_meta[MAX_ATOMS];
__device__ float  g_gl[MAX_CLAUSES];          // gate[c]*leaf[c]
__device__ int    g_chunk_start[NCHUNKS + 1]; // clause-aligned atom ranges
__device__ float  g_empty[NCHUNKS];           // sum of g over EMPTY clauses per chunk

__global__ void cln_setup(const float* __restrict__ w,
                          const float* __restrict__ eta,
                          const float* __restrict__ leaf,
                          const float* __restrict__ gate,
                          const int* __restrict__ fid,
                          const int* __restrict__ csgn,
                          const int* __restrict__ cids,
                          int n_atoms, int n_clauses, int cpc) {
    int i = blockIdx.x * blockDim.x + threadIdx.x;
    const float L2E = 1.4426950408889634f;   // log2(e)
    if (i < n_clauses) g_gl[i] = gate[i] * leaf[i];
    if (i < n_atoms) {
        float sB = (csgn[i] == 0) ? -100.0f : 100.0f;   // sign * B_CONST
        float A2 = -sB * w[i] * L2E;
        float B2 = -sB * (0.01f - eta[i]) * L2E;        // EPS = 0.01
        int cid  = cids[i];
        bool last = (i == n_atoms - 1) || (cids[i + 1] != cid);
        int fz = fid[i] | (last ? 0x80000000 : 0);
        float g = last ? gate[cid] * leaf[cid] : 0.f;
        g_meta[i] = make_float4(A2, B2, __int_as_float(fz), g);
    }
    if (i <= NCHUNKS) {
        int target = i * cpc, lo = 0, hi = n_atoms;
        while (lo < hi) {
            int mid = (lo + hi) >> 1;
            if (cids[mid] < target) lo = mid + 1; else hi = mid;
        }
        g_chunk_start[i] = lo;
    }
}

// Per-chunk constant: sum of g over clauses with NO atoms (their product == 1).
__global__ void cln_empty(const int* __restrict__ cids, int n_atoms, int cpc) {
    int k = threadIdx.x;            // one thread per chunk
    if (k >= NCHUNKS) return;
    float s = 0.f;
    for (int c = k * cpc; c < (k + 1) * cpc; ++c) {
        // clause empty <=> lower_bound(c) == lower_bound(c+1)
        int lo = 0, hi = n_atoms;
        while (lo < hi) { int m = (lo + hi) >> 1; if (cids[m] < c) lo = m + 1; else hi = m; }
        int lo2 = lo, hi2 = n_atoms;
        while (lo2 < hi2) { int m = (lo2 + hi2) >> 1; if (cids[m] < c + 1) lo2 = m + 1; else hi2 = m; }
        if (lo == lo2) s += g_gl[c];
    }
    g_empty[k] = s;
}

__global__ __launch_bounds__(THREADS)
void cln_main(const float* __restrict__ x, float* __restrict__ y, int nfeat) {
    extern __shared__ float xs[];            // ROWS * XPAD floats
    __shared__ float ys[ROWS];

    const int rowBase = blockIdx.x * ROWS;

    // Stage 64 rows of x into shared (coalesced float4 loads, conflict-free stores)
    const int n4 = nfeat >> 2;
    for (int i = threadIdx.x; i < ROWS * n4; i += THREADS) {
        int row = i / n4, f4 = i - row * n4;
        float4 v = reinterpret_cast<const float4*>(
                       x + (size_t)(rowBase + row) * nfeat)[f4];
        float* d = xs + row * XPAD + (f4 << 2);
        d[0] = v.x; d[1] = v.y; d[2] = v.z; d[3] = v.w;
    }
    if (threadIdx.x < ROWS) ys[threadIdx.x] = 0.f;
    __syncthreads();

    const int warp = threadIdx.x >> 5;
    const int lane = threadIdx.x & 31;
    const int chunk = blockIdx.y * WARPS + warp;   // 0..NCHUNKS-1

    const float* xr0 = xs + lane * XPAD;   // lane owns rows lane and lane+32
    const float ec = g_empty[chunk];
    float y0 = ec, y1 = ec;
    float p0 = 1.f, p1 = 1.f;

    const float4* __restrict__ mp = g_meta + g_chunk_start[chunk];
    const int n = g_chunk_start[chunk + 1] - g_chunk_start[chunk];

#define STEP(mm)                                                  \
    {                                                             \
        int fz = __float_as_int((mm).z);                          \
        int f  = fz & 0x7fffffff;                                 \
        float e0 = exp2f(fmaf((mm).x, xr0[f], (mm).y));           \
        float e1 = exp2f(fmaf((mm).x, xr0[f + 32 * XPAD], (mm).y)); \
        p0 = fminf(fmaf(p0, e0, p0), 1e38f);                      \
        p1 = fminf(fmaf(p1, e1, p1), 1e38f);                      \
        if (fz < 0) {           /* last atom of clause: flush */  \
            y0 += __fdividef((mm).w, p0);                         \
            y1 += __fdividef((mm).w, p1);                         \
            p0 = 1.f; p1 = 1.f;                                   \
        }                                                         \
    }

    int i = 0;
    const int n8 = n & ~(UNROLL - 1);
    for (; i < n8; i += UNROLL) {
        float4 mm[UNROLL];
        #pragma unroll
        for (int j = 0; j < UNROLL; ++j) mm[j] = mp[i + j];   // MLP=8 batch
        #pragma unroll
        for (int j = 0; j < UNROLL; ++j) STEP(mm[j]);
    }
    for (; i < n; ++i) {
        float4 m = mp[i];
        STEP(m);
    }
    // chunk is clause-aligned: last atom always flushed, p==1 here.

    atomicAdd(&ys[lane], y0);
    atomicAdd(&ys[lane + 32], y1);
    __syncthreads();
    if (threadIdx.x < ROWS)
        atomicAdd(&y[rowBase + threadIdx.x], ys[threadIdx.x]);
}

extern "C" void kernel_launch(void* const* d_in, const int* in_sizes, int n_in,
                              void* d_out, int out_size) {
    const float* x    = (const float*)d_in[0];
    const float* w    = (const float*)d_in[1];
    const float* eta  = (const float*)d_in[2];
    const float* leaf = (const float*)d_in[3];
    const float* gate = (const float*)d_in[4];
    const int*   fid  = (const int*)d_in[5];
    const int*   csgn = (const int*)d_in[6];
    const int*   cids = (const int*)d_in[7];

    const int n_atoms   = in_sizes[1];
    const int n_clauses = in_sizes[3];
    const int batch     = out_size;
    const int nfeat     = in_sizes[0] / batch;
    const int cpc       = n_clauses / NCHUNKS;

    cudaMemsetAsync(d_out, 0, (size_t)batch * sizeof(float));

    int setup_n = n_atoms;
    if (n_clauses > setup_n)   setup_n = n_clauses;
    if (NCHUNKS + 1 > setup_n) setup_n = NCHUNKS + 1;
    cln_setup<<<(setup_n + 255) / 256, 256>>>(w, eta, leaf, gate, fid, csgn, cids,
                                              n_atoms, n_clauses, cpc);
    cln_empty<<<1, NCHUNKS>>>(cids, n_atoms, cpc);

    size_t smem = (size_t)ROWS * XPAD * sizeof(float);
    cudaFuncSetAttribute(cln_main, cudaFuncAttributeMaxDynamicSharedMemorySize,
                         (int)smem);
    dim3 grid(batch / ROWS, NCHUNKS / WARPS);
    cln_main<<<grid, THREADS, smem>>>(x, (float*)d_out, nfeat);
}

// round 4
// speedup vs baseline: 1.4201x; 1.4201x over previous
#include <cuda_runtime.h>

#define NCHUNKS 32
#define WARPS   8
#define ROWS    64
#define THREADS 256
#define XPAD    257               // smem row stride in floats (conflict-free)
#define MAX_ATOMS   16384
#define MAX_CLAUSES 4096

// Packed per-atom metadata: {A', B', fid|lastFlag(bit31), g_gl[cid] if last}
// arg = A'*x[fid] + B' ;  e = exp2(arg) = exp(-z) ;  sigmoid(z) = 1/(1+e)
// clause value = 1 / prod(1+e) ; flushed when lastFlag set.
__device__ float4 g_meta[MAX_ATOMS];
__device__ float  g_gl[MAX_CLAUSES];          // gate[c]*leaf[c]
__device__ int    g_chunk_start[NCHUNKS + 1]; // clause-aligned atom ranges
__device__ float  g_empty[NCHUNKS];           // sum of g over EMPTY clauses per chunk

__global__ void cln_setup(const float* __restrict__ w,
                          const float* __restrict__ eta,
                          const float* __restrict__ leaf,
                          const float* __restrict__ gate,
                          const int* __restrict__ fid,
                          const int* __restrict__ csgn,
                          const int* __restrict__ cids,
                          int n_atoms, int n_clauses, int cpc) {
    int i = blockIdx.x * blockDim.x + threadIdx.x;
    const float L2E = 1.4426950408889634f;   // log2(e)
    if (i < n_clauses) g_gl[i] = gate[i] * leaf[i];
    if (i < NCHUNKS)   g_empty[i] = 0.f;
    if (i < n_atoms) {
        float sB = (csgn[i] == 0) ? -100.0f : 100.0f;   // sign * B_CONST
        float A2 = -sB * w[i] * L2E;
        float B2 = -sB * (0.01f - eta[i]) * L2E;        // EPS = 0.01
        int cid  = cids[i];
        bool last = (i == n_atoms - 1) || (cids[i + 1] != cid);
        int fz = fid[i] | (last ? 0x80000000 : 0);
        float g = last ? gate[cid] * leaf[cid] : 0.f;
        g_meta[i] = make_float4(A2, B2, __int_as_float(fz), g);
    }
    if (i <= NCHUNKS) {
        int target = i * cpc, lo = 0, hi = n_atoms;
        while (lo < hi) {
            int mid = (lo + hi) >> 1;
            if (cids[mid] < target) lo = mid + 1; else hi = mid;
        }
        g_chunk_start[i] = lo;
    }
}

// One thread per clause: empty <=> no atom has this cid. Parallel, ~1us.
__global__ void cln_empty(const int* __restrict__ cids,
                          int n_atoms, int n_clauses, int cpc) {
    int c = blockIdx.x * blockDim.x + threadIdx.x;
    if (c >= n_clauses) return;
    int lo = 0, hi = n_atoms;
    while (lo < hi) {
        int m = (lo + hi) >> 1;
        if (cids[m] < c) lo = m + 1; else hi = m;
    }
    bool empty = (lo == n_atoms) || (cids[lo] != c);
    if (empty) atomicAdd(&g_empty[c / cpc], g_gl[c]);
}

__global__ __launch_bounds__(THREADS)
void cln_main(const float* __restrict__ x, float* __restrict__ y, int nfeat) {
    extern __shared__ float xs[];            // ROWS * XPAD floats
    __shared__ float ys[ROWS];

    const int rowBase = blockIdx.x * ROWS;

    // Stage 64 rows of x into shared (coalesced float4 loads)
    const int n4 = nfeat >> 2;
    for (int i = threadIdx.x; i < ROWS * n4; i += THREADS) {
        int row = i / n4, f4 = i - row * n4;
        float4 v = reinterpret_cast<const float4*>(
                       x + (size_t)(rowBase + row) * nfeat)[f4];
        float* d = xs + row * XPAD + (f4 << 2);
        d[0] = v.x; d[1] = v.y; d[2] = v.z; d[3] = v.w;
    }
    if (threadIdx.x < ROWS) ys[threadIdx.x] = 0.f;
    __syncthreads();

    const int warp = threadIdx.x >> 5;
    const int lane = threadIdx.x & 31;
    const int chunk = blockIdx.y * WARPS + warp;   // 0..NCHUNKS-1

    const float* xr0 = xs + lane * XPAD;   // lane owns rows lane and lane+32
    const float ec = g_empty[chunk];
    float y0 = ec, y1 = ec;
    float p0 = 1.f, p1 = 1.f;              // p >= 1 always; inf is safe, NaN impossible

#define STEP(mm)                                                      \
    {                                                                 \
        int fz = __float_as_int((mm).z);                              \
        int f  = fz & 0x7fffffff;                                     \
        float e0 = fmaxf(exp2f(fmaf((mm).x, xr0[f], (mm).y)), 1e-37f);\
        float e1 = fmaxf(exp2f(fmaf((mm).x, xr0[f + 32 * XPAD], (mm).y)), 1e-37f);\
        p0 = fmaf(p0, e0, p0);                                        \
        p1 = fmaf(p1, e1, p1);                                        \
        if (fz < 0) {                /* last atom of clause: flush */ \
            float r0 = __fdividef(1.0f, p0);                          \
            float r1 = __fdividef(1.0f, p1);                          \
            y0 = fmaf((mm).w, r0, y0);                                \
            y1 = fmaf((mm).w, r1, y1);                                \
            p0 = 1.f; p1 = 1.f;                                       \
        }                                                             \
    }

    const float4* __restrict__ mp = g_meta + g_chunk_start[chunk];
    const int n = g_chunk_start[chunk + 1] - g_chunk_start[chunk];

    int i = 0;
    for (; i + 4 <= n; i += 4) {
        float4 m0 = mp[i], m1 = mp[i + 1], m2 = mp[i + 2], m3 = mp[i + 3];
        STEP(m0); STEP(m1); STEP(m2); STEP(m3);
    }
    for (; i < n; ++i) {
        float4 m = mp[i];
        STEP(m);
    }
    // chunk is clause-aligned: last atom always flushes, p==1 here.

    atomicAdd(&ys[lane], y0);
    atomicAdd(&ys[lane + 32], y1);
    __syncthreads();
    if (threadIdx.x < ROWS)
        atomicAdd(&y[rowBase + threadIdx.x], ys[threadIdx.x]);
}

extern "C" void kernel_launch(void* const* d_in, const int* in_sizes, int n_in,
                              void* d_out, int out_size) {
    const float* x    = (const float*)d_in[0];
    const float* w    = (const float*)d_in[1];
    const float* eta  = (const float*)d_in[2];
    const float* leaf = (const float*)d_in[3];
    const float* gate = (const float*)d_in[4];
    const int*   fid  = (const int*)d_in[5];
    const int*   csgn = (const int*)d_in[6];
    const int*   cids = (const int*)d_in[7];

    const int n_atoms   = in_sizes[1];
    const int n_clauses = in_sizes[3];
    const int batch     = out_size;
    const int nfeat     = in_sizes[0] / batch;
    const int cpc       = n_clauses / NCHUNKS;

    cudaMemsetAsync(d_out, 0, (size_t)batch * sizeof(float));

    int setup_n = n_atoms;
    if (n_clauses > setup_n)   setup_n = n_clauses;
    if (NCHUNKS + 1 > setup_n) setup_n = NCHUNKS + 1;
    cln_setup<<<(setup_n + 255) / 256, 256>>>(w, eta, leaf, gate, fid, csgn, cids,
                                              n_atoms, n_clauses, cpc);
    cln_empty<<<(n_clauses + 255) / 256, 256>>>(cids, n_atoms, n_clauses, cpc);

    size_t smem = (size_t)ROWS * XPAD * sizeof(float);
    cudaFuncSetAttribute(cln_main, cudaFuncAttributeMaxDynamicSharedMemorySize,
                         (int)smem);
    dim3 grid(batch / ROWS, NCHUNKS / WARPS);
    cln_main<<<grid, THREADS, smem>>>(x, (float*)d_out, nfeat);
}

// round 5
// speedup vs baseline: 1.6889x; 1.1892x over previous
#include <cuda_runtime.h>

#define NCHUNKS 32
#define WARPS   8
#define ROWS    64
#define THREADS 256
#define XPAD    257               // smem row stride in floats (conflict-free)
#define MAX_ATOMS   16384
#define MAX_CLAUSES 4096

// Packed per-atom metadata: {A', B', fid|lastFlag(bit31), gate*leaf[cid] if last}
// arg = A'*x[fid] + B' ;  e = exp2(arg) = exp(-z) ;  sigmoid(z) = 1/(1+e)
// clause value = 1 / prod(1+e) ; accumulated when lastFlag set.
__device__ float4 g_meta[MAX_ATOMS];
__device__ int    g_chunk_start[NCHUNKS + 1]; // clause-aligned atom ranges
__device__ float  g_empty[NCHUNKS];           // sum of g over EMPTY clauses per chunk

__global__ void cln_setup(const float* __restrict__ w,
                          const float* __restrict__ eta,
                          const float* __restrict__ leaf,
                          const float* __restrict__ gate,
                          const int* __restrict__ fid,
                          const int* __restrict__ csgn,
                          const int* __restrict__ cids,
                          int n_atoms, int n_clauses, int cpc) {
    int i = blockIdx.x * blockDim.x + threadIdx.x;
    const float L2E = 1.4426950408889634f;   // log2(e)
    if (i < n_atoms) {
        float sB = (csgn[i] == 0) ? -100.0f : 100.0f;   // sign * B_CONST
        float A2 = -sB * w[i] * L2E;
        float B2 = -sB * (0.01f - eta[i]) * L2E;        // EPS = 0.01
        int cid  = cids[i];
        int nxt  = (i == n_atoms - 1) ? n_clauses : cids[i + 1];
        bool last = (nxt != cid);
        int fz = fid[i] | (last ? 0x80000000 : 0);
        float g = last ? gate[cid] * leaf[cid] : 0.f;
        g_meta[i] = make_float4(A2, B2, __int_as_float(fz), g);
        // empty clauses in the gap (cid, nxt): their product is 1
        if (last) {
            for (int c = cid + 1; c < nxt; ++c)
                atomicAdd(&g_empty[c / cpc], gate[c] * leaf[c]);
        }
        // head gap [0, cids[0])
        if (i == 0) {
            for (int c = 0; c < cid; ++c)
                atomicAdd(&g_empty[c / cpc], gate[c] * leaf[c]);
        }
    }
    if (i <= NCHUNKS) {
        int target = i * cpc, lo = 0, hi = n_atoms;
        while (lo < hi) {
            int mid = (lo + hi) >> 1;
            if (cids[mid] < target) lo = mid + 1; else hi = mid;
        }
        g_chunk_start[i] = lo;
    }
}

__global__ __launch_bounds__(THREADS, 3)
void cln_main(const float* __restrict__ x, float* __restrict__ y, int nfeat) {
    extern __shared__ float xs[];            // ROWS * XPAD floats
    __shared__ float ys[ROWS];

    const int rowBase = blockIdx.x * ROWS;

    // Stage 64 rows of x into shared (coalesced float4 loads)
    const int n4 = nfeat >> 2;
    for (int i = threadIdx.x; i < ROWS * n4; i += THREADS) {
        int row = i / n4, f4 = i - row * n4;
        float4 v = reinterpret_cast<const float4*>(
                       x + (size_t)(rowBase + row) * nfeat)[f4];
        float* d = xs + row * XPAD + (f4 << 2);
        d[0] = v.x; d[1] = v.y; d[2] = v.z; d[3] = v.w;
    }
    if (threadIdx.x < ROWS) ys[threadIdx.x] = 0.f;
    __syncthreads();

    const int warp = threadIdx.x >> 5;
    const int lane = threadIdx.x & 31;
    const int chunk = blockIdx.y * WARPS + warp;   // 0..NCHUNKS-1

    const float* xr0 = xs + lane * XPAD;   // lane owns rows lane and lane+32
    const float ec = g_empty[chunk];
    float y0 = ec, y1 = ec;
    float p0 = 1.f, p1 = 1.f;              // p >= 1 always

    const float4* __restrict__ mp = g_meta + g_chunk_start[chunk];
    const int n = g_chunk_start[chunk + 1] - g_chunk_start[chunk];

    // e clamped away from 0 so p==inf never meets e==0 (no NaN); p may reach
    // inf, then rcp gives 0 which matches reference underflow-to-zero.
#define EVAL(mm, f, off) fmaxf(exp2f(fmaf((mm).x, xr0[(f) + (off)], (mm).y)), 1e-37f)

    int i = 0;
    for (; i + 4 <= n; i += 4) {
        float4 m0 = mp[i], m1 = mp[i + 1], m2 = mp[i + 2], m3 = mp[i + 3];
        int fz0 = __float_as_int(m0.z), fz1 = __float_as_int(m1.z);
        int fz2 = __float_as_int(m2.z), fz3 = __float_as_int(m3.z);
        int f0 = fz0 & 0x7fffffff, f1 = fz1 & 0x7fffffff;
        int f2 = fz2 & 0x7fffffff, f3 = fz3 & 0x7fffffff;

        // 8 independent exponentials (pipelined MUFU)
        float e00 = EVAL(m0, f0, 0),        e01 = EVAL(m1, f1, 0);
        float e02 = EVAL(m2, f2, 0),        e03 = EVAL(m3, f3, 0);
        float e10 = EVAL(m0, f0, 32 * XPAD), e11 = EVAL(m1, f1, 32 * XPAD);
        float e12 = EVAL(m2, f2, 32 * XPAD), e13 = EVAL(m3, f3, 32 * XPAD);

        // branchless p-chains with SEL resets; q's keep pre-reset values
        float q00 = fmaf(p0, e00, p0);  p0 = (fz0 < 0) ? 1.f : q00;
        float q01 = fmaf(p0, e01, p0);  p0 = (fz1 < 0) ? 1.f : q01;
        float q02 = fmaf(p0, e02, p0);  p0 = (fz2 < 0) ? 1.f : q02;
        float q03 = fmaf(p0, e03, p0);  p0 = (fz3 < 0) ? 1.f : q03;
        float q10 = fmaf(p1, e10, p1);  p1 = (fz0 < 0) ? 1.f : q10;
        float q11 = fmaf(p1, e11, p1);  p1 = (fz1 < 0) ? 1.f : q11;
        float q12 = fmaf(p1, e12, p1);  p1 = (fz2 < 0) ? 1.f : q12;
        float q13 = fmaf(p1, e13, p1);  p1 = (fz3 < 0) ? 1.f : q13;

        // rare path: flush finished clauses (one branch per 4 atoms)
        if ((fz0 | fz1 | fz2 | fz3) < 0) {
            if (fz0 < 0) { y0 = fmaf(m0.w, __fdividef(1.f, q00), y0);
                           y1 = fmaf(m0.w, __fdividef(1.f, q10), y1); }
            if (fz1 < 0) { y0 = fmaf(m1.w, __fdividef(1.f, q01), y0);
                           y1 = fmaf(m1.w, __fdividef(1.f, q11), y1); }
            if (fz2 < 0) { y0 = fmaf(m2.w, __fdividef(1.f, q02), y0);
                           y1 = fmaf(m2.w, __fdividef(1.f, q12), y1); }
            if (fz3 < 0) { y0 = fmaf(m3.w, __fdividef(1.f, q03), y0);
                           y1 = fmaf(m3.w, __fdividef(1.f, q13), y1); }
        }
    }
    for (; i < n; ++i) {
        float4 m = mp[i];
        int fz = __float_as_int(m.z);
        int f  = fz & 0x7fffffff;
        float e0 = EVAL(m, f, 0), e1 = EVAL(m, f, 32 * XPAD);
        float q0 = fmaf(p0, e0, p0), q1 = fmaf(p1, e1, p1);
        if (fz < 0) {
            y0 = fmaf(m.w, __fdividef(1.f, q0), y0);
            y1 = fmaf(m.w, __fdividef(1.f, q1), y1);
            p0 = 1.f; p1 = 1.f;
        } else { p0 = q0; p1 = q1; }
    }
    // chunk is clause-aligned: last atom always flushes.

    atomicAdd(&ys[lane], y0);
    atomicAdd(&ys[lane + 32], y1);
    __syncthreads();
    if (threadIdx.x < ROWS)
        atomicAdd(&y[rowBase + threadIdx.x], ys[threadIdx.x]);
}

extern "C" void kernel_launch(void* const* d_in, const int* in_sizes, int n_in,
                              void* d_out, int out_size) {
    const float* x    = (const float*)d_in[0];
    const float* w    = (const float*)d_in[1];
    const float* eta  = (const float*)d_in[2];
    const float* leaf = (const float*)d_in[3];
    const float* gate = (const float*)d_in[4];
    const int*   fid  = (const int*)d_in[5];
    const int*   csgn = (const int*)d_in[6];
    const int*   cids = (const int*)d_in[7];

    const int n_atoms   = in_sizes[1];
    const int n_clauses = in_sizes[3];
    const int batch     = out_size;
    const int nfeat     = in_sizes[0] / batch;
    const int cpc       = n_clauses / NCHUNKS;

    cudaMemsetAsync(d_out, 0, (size_t)batch * sizeof(float));
    void* empty_ptr = nullptr;
    cudaGetSymbolAddress(&empty_ptr, g_empty);
    cudaMemsetAsync(empty_ptr, 0, NCHUNKS * sizeof(float));

    int setup_n = (n_atoms > n_clauses ? n_atoms : n_clauses);
    if (NCHUNKS + 1 > setup_n) setup_n = NCHUNKS + 1;
    cln_setup<<<(setup_n + 255) / 256, 256>>>(w, eta, leaf, gate, fid, csgn, cids,
                                              n_atoms, n_clauses, cpc);

    size_t smem = (size_t)ROWS * XPAD * sizeof(float);
    cudaFuncSetAttribute(cln_main, cudaFuncAttributeMaxDynamicSharedMemorySize,
                         (int)smem);
    dim3 grid(batch / ROWS, NCHUNKS / WARPS);
    cln_main<<<grid, THREADS, smem>>>(x, (float*)d_out, nfeat);
}

// round 6
// speedup vs baseline: 2.4720x; 1.4637x over previous
#include <cuda_runtime.h>

#define NCHUNKS 32
#define WARPS   32
#define ROWS    64
#define THREADS 1024
#define XPAD    257               // smem row stride in floats (conflict-free)
#define MAX_ATOMS   16384
#define MAX_CLAUSES 4096

// Packed per-atom metadata: {A', B', fid|lastFlag(bit31), gate*leaf[cid] if last}
// arg = A'*x[fid] + B' ;  e = exp2(arg) = exp(-z) ;  sigmoid(z) = 1/(1+e)
// clause value = 1 / prod(1+e) ; accumulated when lastFlag set.
__device__ float4 g_meta[MAX_ATOMS];
__device__ int    g_chunk_start[NCHUNKS + 1]; // clause-aligned atom ranges
__device__ float  g_empty[NCHUNKS];           // sum of g over EMPTY clauses per chunk

__global__ void cln_setup(const float* __restrict__ w,
                          const float* __restrict__ eta,
                          const float* __restrict__ leaf,
                          const float* __restrict__ gate,
                          const int* __restrict__ fid,
                          const int* __restrict__ csgn,
                          const int* __restrict__ cids,
                          int n_atoms, int n_clauses, int cpc) {
    int i = blockIdx.x * blockDim.x + threadIdx.x;
    const float L2E = 1.4426950408889634f;   // log2(e)
    if (i < n_atoms) {
        float sB = (csgn[i] == 0) ? -100.0f : 100.0f;   // sign * B_CONST
        float A2 = -sB * w[i] * L2E;
        float B2 = -sB * (0.01f - eta[i]) * L2E;        // EPS = 0.01
        int cid  = cids[i];
        int nxt  = (i == n_atoms - 1) ? n_clauses : cids[i + 1];
        bool last = (nxt != cid);
        int fz = fid[i] | (last ? 0x80000000 : 0);
        float g = last ? gate[cid] * leaf[cid] : 0.f;
        g_meta[i] = make_float4(A2, B2, __int_as_float(fz), g);
        // empty clauses in the gap (cid, nxt): their product is 1
        if (last) {
            for (int c = cid + 1; c < nxt; ++c)
                atomicAdd(&g_empty[c / cpc], gate[c] * leaf[c]);
        }
        // head gap [0, cids[0])
        if (i == 0) {
            for (int c = 0; c < cid; ++c)
                atomicAdd(&g_empty[c / cpc], gate[c] * leaf[c]);
        }
    }
    if (i <= NCHUNKS) {
        int target = i * cpc, lo = 0, hi = n_atoms;
        while (lo < hi) {
            int mid = (lo + hi) >> 1;
            if (cids[mid] < target) lo = mid + 1; else hi = mid;
        }
        g_chunk_start[i] = lo;
    }
}

__global__ __launch_bounds__(THREADS, 1)
void cln_main(const float* __restrict__ x, float* __restrict__ y, int nfeat) {
    extern __shared__ float xs[];            // ROWS * XPAD floats
    __shared__ float ys[ROWS];

    const int rowBase = blockIdx.x * ROWS;

    // Stage 64 rows of x into shared (coalesced float4 loads)
    const int n4 = nfeat >> 2;
    for (int i = threadIdx.x; i < ROWS * n4; i += THREADS) {
        int row = i / n4, f4 = i - row * n4;
        float4 v = reinterpret_cast<const float4*>(
                       x + (size_t)(rowBase + row) * nfeat)[f4];
        float* d = xs + row * XPAD + (f4 << 2);
        d[0] = v.x; d[1] = v.y; d[2] = v.z; d[3] = v.w;
    }
    if (threadIdx.x < ROWS) ys[threadIdx.x] = 0.f;
    __syncthreads();

    const int chunk = threadIdx.x >> 5;    // warp == chunk, 0..31
    const int lane  = threadIdx.x & 31;

    const float* xr0 = xs + lane * XPAD;   // lane owns rows lane and lane+32
    const float ec = g_empty[chunk];
    float y0 = ec, y1 = ec;
    float p0 = 1.f, p1 = 1.f;              // p >= 1 always

    const float4* __restrict__ mp = g_meta + g_chunk_start[chunk];
    const int n = g_chunk_start[chunk + 1] - g_chunk_start[chunk];

    // e clamped away from 0 so p==inf never meets e==0 (no NaN); p may reach
    // inf, then rcp gives 0 which matches reference underflow-to-zero.
#define EVAL(mm, f, off) fmaxf(exp2f(fmaf((mm).x, xr0[(f) + (off)], (mm).y)), 1e-37f)

    int i = 0;
    for (; i + 4 <= n; i += 4) {
        float4 m0 = mp[i], m1 = mp[i + 1], m2 = mp[i + 2], m3 = mp[i + 3];
        int fz0 = __float_as_int(m0.z), fz1 = __float_as_int(m1.z);
        int fz2 = __float_as_int(m2.z), fz3 = __float_as_int(m3.z);
        int f0 = fz0 & 0x7fffffff, f1 = fz1 & 0x7fffffff;
        int f2 = fz2 & 0x7fffffff, f3 = fz3 & 0x7fffffff;

        // 8 independent exponentials (pipelined MUFU)
        float e00 = EVAL(m0, f0, 0),        e01 = EVAL(m1, f1, 0);
        float e02 = EVAL(m2, f2, 0),        e03 = EVAL(m3, f3, 0);
        float e10 = EVAL(m0, f0, 32 * XPAD), e11 = EVAL(m1, f1, 32 * XPAD);
        float e12 = EVAL(m2, f2, 32 * XPAD), e13 = EVAL(m3, f3, 32 * XPAD);

        // branchless p-chains with SEL resets; q's keep pre-reset values
        float q00 = fmaf(p0, e00, p0);  p0 = (fz0 < 0) ? 1.f : q00;
        float q01 = fmaf(p0, e01, p0);  p0 = (fz1 < 0) ? 1.f : q01;
        float q02 = fmaf(p0, e02, p0);  p0 = (fz2 < 0) ? 1.f : q02;
        float q03 = fmaf(p0, e03, p0);  p0 = (fz3 < 0) ? 1.f : q03;
        float q10 = fmaf(p1, e10, p1);  p1 = (fz0 < 0) ? 1.f : q10;
        float q11 = fmaf(p1, e11, p1);  p1 = (fz1 < 0) ? 1.f : q11;
        float q12 = fmaf(p1, e12, p1);  p1 = (fz2 < 0) ? 1.f : q12;
        float q13 = fmaf(p1, e13, p1);  p1 = (fz3 < 0) ? 1.f : q13;

        // rare path: flush finished clauses (one warp-uniform branch / 4 atoms)
        if ((fz0 | fz1 | fz2 | fz3) < 0) {
            if (fz0 < 0) { y0 = fmaf(m0.w, __fdividef(1.f, q00), y0);
                           y1 = fmaf(m0.w, __fdividef(1.f, q10), y1); }
            if (fz1 < 0) { y0 = fmaf(m1.w, __fdividef(1.f, q01), y0);
                           y1 = fmaf(m1.w, __fdividef(1.f, q11), y1); }
            if (fz2 < 0) { y0 = fmaf(m2.w, __fdividef(1.f, q02), y0);
                           y1 = fmaf(m2.w, __fdividef(1.f, q12), y1); }
            if (fz3 < 0) { y0 = fmaf(m3.w, __fdividef(1.f, q03), y0);
                           y1 = fmaf(m3.w, __fdividef(1.f, q13), y1); }
        }
    }
    for (; i < n; ++i) {
        float4 m = mp[i];
        int fz = __float_as_int(m.z);
        int f  = fz & 0x7fffffff;
        float e0 = EVAL(m, f, 0), e1 = EVAL(m, f, 32 * XPAD);
        float q0 = fmaf(p0, e0, p0), q1 = fmaf(p1, e1, p1);
        if (fz < 0) {
            y0 = fmaf(m.w, __fdividef(1.f, q0), y0);
            y1 = fmaf(m.w, __fdividef(1.f, q1), y1);
            p0 = 1.f; p1 = 1.f;
        } else { p0 = q0; p1 = q1; }
    }
    // chunk is clause-aligned: last atom always flushes.

    atomicAdd(&ys[lane], y0);
    atomicAdd(&ys[lane + 32], y1);
    __syncthreads();
    if (threadIdx.x < ROWS)
        y[rowBase + threadIdx.x] = ys[threadIdx.x];   // sole writer per row
}

extern "C" void kernel_launch(void* const* d_in, const int* in_sizes, int n_in,
                              void* d_out, int out_size) {
    const float* x    = (const float*)d_in[0];
    const float* w    = (const float*)d_in[1];
    const float* eta  = (const float*)d_in[2];
    const float* leaf = (const float*)d_in[3];
    const float* gate = (const float*)d_in[4];
    const int*   fid  = (const int*)d_in[5];
    const int*   csgn = (const int*)d_in[6];
    const int*   cids = (const int*)d_in[7];

    const int n_atoms   = in_sizes[1];
    const int n_clauses = in_sizes[3];
    const int batch     = out_size;
    const int nfeat     = in_sizes[0] / batch;
    const int cpc       = n_clauses / NCHUNKS;

    void* empty_ptr = nullptr;
    cudaGetSymbolAddress(&empty_ptr, g_empty);
    cudaMemsetAsync(empty_ptr, 0, NCHUNKS * sizeof(float));

    int setup_n = (n_atoms > n_clauses ? n_atoms : n_clauses);
    if (NCHUNKS + 1 > setup_n) setup_n = NCHUNKS + 1;
    cln_setup<<<(setup_n + 255) / 256, 256>>>(w, eta, leaf, gate, fid, csgn, cids,
                                              n_atoms, n_clauses, cpc);

    size_t smem = (size_t)ROWS * XPAD * sizeof(float);
    cudaFuncSetAttribute(cln_main, cudaFuncAttributeMaxDynamicSharedMemorySize,
                         (int)smem);
    cln_main<<<batch / ROWS, THREADS, smem>>>(x, (float*)d_out, nfeat);
}